// round 9
// baseline (speedup 1.0000x reference)
#include <cuda_runtime.h>

// FWHT (11 stages, N=2048) + sign flip on last quarter, batch 16384.
// TWO warps per row, 32 fp32/thread. Per half-row (fixed bit10):
//   bits 0,1  -> register-local (inside float4)
//   bits 2..6 -> warp shuffles (5 stages x 32 values)
//   bits 7,8,9-> register-local across r (3 bits)
//   bit 10    -> one shared-memory half-exchange between the warp pair
// Scale (1/sqrt2)^11 = 2^-5.5 folded into store; sign<0 iff i>=1536 <=> (bit10 & bit9).

__global__ void __launch_bounds__(256)
fwht_sign_kernel2(const float* __restrict__ in, float* __restrict__ out, int rows) {
    __shared__ float sbuf[4][2048];          // 4 rows per 256-thread block, 32 KB

    const int warp     = threadIdx.x >> 5;   // 0..7
    const int lane     = threadIdx.x & 31;
    const int rowLocal = warp >> 1;          // 0..3
    const int half     = warp & 1;           // bit 10 of the global index
    const int row      = blockIdx.x * 4 + rowLocal;
    const bool active  = (row < rows);

    float v[32];

    if (active) {
        const float4* __restrict__ src =
            reinterpret_cast<const float4*>(in) + (size_t)row * 512 + half * 256;

        // Coalesced load: 8 x float4, each instr covers 512 contiguous bytes.
        #pragma unroll
        for (int r = 0; r < 8; r++) {
            float4 f = src[r * 32 + lane];
            v[4*r+0] = f.x; v[4*r+1] = f.y; v[4*r+2] = f.z; v[4*r+3] = f.w;
        }

        // Stages bit0, bit1 (inside the float4).
        #pragma unroll
        for (int r = 0; r < 8; r++) {
            float a0 = v[4*r+0], a1 = v[4*r+1], a2 = v[4*r+2], a3 = v[4*r+3];
            float b0 = a0 + a1, b1 = a0 - a1, b2 = a2 + a3, b3 = a2 - a3;
            v[4*r+0] = b0 + b2;
            v[4*r+1] = b1 + b3;
            v[4*r+2] = b0 - b2;
            v[4*r+3] = b1 - b3;
        }

        // Stages bits 2..6 (lane bits) via warp shuffles.
        #pragma unroll
        for (int h = 1; h <= 16; h <<= 1) {
            const bool upper = (lane & h) != 0;
            #pragma unroll
            for (int k = 0; k < 32; k++) {
                float o = __shfl_xor_sync(0xffffffffu, v[k], h);
                v[k] = upper ? (o - v[k]) : (v[k] + o);
            }
        }

        // Stages bits 7,8,9 (r bits), register-local.
        #pragma unroll
        for (int rh = 1; rh <= 4; rh <<= 1) {
            #pragma unroll
            for (int r = 0; r < 8; r++) {
                if (r & rh) continue;
                #pragma unroll
                for (int c = 0; c < 4; c++) {
                    float a = v[4*r+c];
                    float b = v[4*(r|rh)+c];
                    v[4*r+c]      = a + b;
                    v[4*(r|rh)+c] = a - b;
                }
            }
        }

        // Publish own half to shared memory (conflict-free STS.128).
        float4* sb = reinterpret_cast<float4*>(sbuf[rowLocal]);
        #pragma unroll
        for (int r = 0; r < 8; r++) {
            float4 f;
            f.x = v[4*r+0]; f.y = v[4*r+1]; f.z = v[4*r+2]; f.w = v[4*r+3];
            sb[half * 256 + r * 32 + lane] = f;
        }
    }

    __syncthreads();

    if (active) {
        const float4* sb = reinterpret_cast<const float4*>(sbuf[rowLocal]);
        float4* __restrict__ dst =
            reinterpret_cast<float4*>(out) + (size_t)row * 512 + half * 256;

        const float S = 0.022097086912079612f;   // (1/sqrt(2))^11

        // Stage bit10 from partner half + scale/sign + coalesced store.
        #pragma unroll
        for (int r = 0; r < 8; r++) {
            float4 p = sb[(half ^ 1) * 256 + r * 32 + lane];
            float4 o;
            if (half == 0) {           // out = a + b
                o.x = v[4*r+0] + p.x; o.y = v[4*r+1] + p.y;
                o.z = v[4*r+2] + p.z; o.w = v[4*r+3] + p.w;
            } else {                   // out = a - b  (a = partner's low half)
                o.x = p.x - v[4*r+0]; o.y = p.y - v[4*r+1];
                o.z = p.z - v[4*r+2]; o.w = p.w - v[4*r+3];
            }
            // index = half*1024 + r*128 + ... ; negative iff half==1 && r>=4
            const float s = (half == 1 && r >= 4) ? -S : S;
            o.x *= s; o.y *= s; o.z *= s; o.w *= s;
            dst[r * 32 + lane] = o;
        }
    }
}

extern "C" void kernel_launch(void* const* d_in, const int* in_sizes, int n_in,
                              void* d_out, int out_size) {
    const float* x = (const float*)d_in[0];
    float* out = (float*)d_out;
    const int rows   = in_sizes[0] / 2048;     // 16384
    const int blocks = (rows + 3) / 4;         // 4 rows per 256-thread block
    fwht_sign_kernel2<<<blocks, 256>>>(x, out, rows);
}

// round 10
// speedup vs baseline: 1.0007x; 1.0007x over previous
#include <cuda_runtime.h>

// FWHT (11 stages, N=2048) + sign flip on last quarter, batch 16384.
// Two warps per row, 32 fp32/thread, k = 4r+c register index.
//
// Initial index bits: b0,b1 = k0,k1 ; b2..b6 = lane0..4 ; b7,b8,b9 = k2,k3,k4 ; b10 = warp half.
// Stage plan (butterflies commute):
//   1) b0,b1 local (radix-4 inside float4)
//   2) b7,b8,b9 local (register bits k2..k4)
//   3) b2..b6 via swap-shuffle: ONE shfl per register pair (16/stage, 80 total vs 160),
//      which swaps lane-bit h with register-bit h in the index mapping.
// Final in-warp layout: idx = (lane&3) | (k<<2) | ((lane>>2)<<7).
// The bit-10 exchange through smem doubles as the layout repair: STS scrambled
// (padded, conflict-free), named barrier per warp pair, LDS linear + bit-10
// butterfly + sign/scale + coalesced STG.128.

__global__ void __launch_bounds__(256, 4)
fwht_sign_kernel3(const float* __restrict__ in, float* __restrict__ out, int rows) {
    // 8 half-row buffers of 1024 floats padded by 4 per 128 -> 1056. 33,792 B.
    __shared__ float sbuf[8][1056];

    const int warp     = threadIdx.x >> 5;
    const int lane     = threadIdx.x & 31;
    const int rowLocal = warp >> 1;          // 0..3
    const int half     = warp & 1;           // index bit 10
    const int row      = blockIdx.x * 4 + rowLocal;
    const bool active  = (row < rows);

    float v[32];

    if (active) {
        const float4* __restrict__ src =
            reinterpret_cast<const float4*>(in) + (size_t)row * 512 + half * 256;

        // Coalesced load: 8 x float4 (each warp instr covers 512 contiguous bytes).
        #pragma unroll
        for (int r = 0; r < 8; r++) {
            float4 f = src[r * 32 + lane];
            v[4*r+0] = f.x; v[4*r+1] = f.y; v[4*r+2] = f.z; v[4*r+3] = f.w;
        }

        // Bits 0,1: radix-4 inside each float4 (register bits k0,k1).
        #pragma unroll
        for (int q = 0; q < 32; q += 4) {
            float a0 = v[q+0], a1 = v[q+1], a2 = v[q+2], a3 = v[q+3];
            float b0 = a0 + a1, b1 = a0 - a1, b2 = a2 + a3, b3 = a2 - a3;
            v[q+0] = b0 + b2;
            v[q+1] = b1 + b3;
            v[q+2] = b0 - b2;
            v[q+3] = b1 - b3;
        }

        // Bits 7,8,9: register-local (register bits k2,k3,k4).
        #pragma unroll
        for (int m = 4; m <= 16; m <<= 1) {
            #pragma unroll
            for (int k = 0; k < 32; k++) {
                if (k & m) continue;
                float a = v[k], b = v[k|m];
                v[k]   = a + b;
                v[k|m] = a - b;
            }
        }

        // Bits 2..6: swap-shuffle stages. One SHFL per register pair.
        // Stage s: lane bit h=1<<s exchanges roles with register bit 1<<s.
        #pragma unroll
        for (int s = 0; s < 5; s++) {
            const int  h  = 1 << s;
            const bool up = (lane & h) != 0;
            #pragma unroll
            for (int k = 0; k < 32; k++) {
                if (k & h) continue;
                const int ko = k | h;
                float send = up ? v[k] : v[ko];
                float t = __shfl_xor_sync(0xffffffffu, send, h);
                float a = up ? t      : v[k];   // x (bit h = 0 side)
                float b = up ? v[ko]  : t;      // y (bit h = 1 side)
                v[k]  = a + b;
                v[ko] = a - b;
            }
        }

        // Publish to smem in linear (padded) index order, undoing the scramble.
        // idx = (lane&3) | (k<<2) | ((lane>>2)<<7); padded addr = idx + 4*(idx>>7).
        {
            float* sb = sbuf[rowLocal * 2 + half];
            const int base = (lane & 3) + (lane >> 2) * 132;
            #pragma unroll
            for (int k = 0; k < 32; k++)
                sb[base + 4 * k] = v[k];   // conflict-free STS.32 per k
        }
    }

    // Sync only this warp pair (64 threads), ids 1..4.
    asm volatile("bar.sync %0, 64;" :: "r"(rowLocal + 1) : "memory");

    if (active) {
        const float* slo = sbuf[rowLocal * 2 + 0];
        const float* shi = sbuf[rowLocal * 2 + 1];
        float4* __restrict__ dst =
            reinterpret_cast<float4*>(out) + (size_t)row * 512 + half * 256;

        const float S = 0.022097086912079612f;   // (1/sqrt(2))^11

        // Bit-10 butterfly + sign + scale + coalesced store.
        // Output idx = half*1024 + g*128 + lane*4 ; negative iff half==1 && g>=4.
        #pragma unroll
        for (int g = 0; g < 8; g++) {
            const int a = g * 132 + lane * 4;   // padded smem addr (conflict-free LDS.128)
            float4 lo = *reinterpret_cast<const float4*>(slo + a);
            float4 hi = *reinterpret_cast<const float4*>(shi + a);
            const float s = (half == 1 && g >= 4) ? -S : S;
            float4 o;
            if (half == 0) {
                o.x = (lo.x + hi.x) * s; o.y = (lo.y + hi.y) * s;
                o.z = (lo.z + hi.z) * s; o.w = (lo.w + hi.w) * s;
            } else {
                o.x = (lo.x - hi.x) * s; o.y = (lo.y - hi.y) * s;
                o.z = (lo.z - hi.z) * s; o.w = (lo.w - hi.w) * s;
            }
            dst[g * 32 + lane] = o;
        }
    }
}

extern "C" void kernel_launch(void* const* d_in, const int* in_sizes, int n_in,
                              void* d_out, int out_size) {
    const float* x = (const float*)d_in[0];
    float* out = (float*)d_out;
    const int rows   = in_sizes[0] / 2048;     // 16384
    const int blocks = (rows + 3) / 4;         // 4 rows per 256-thread block
    fwht_sign_kernel3<<<blocks, 256>>>(x, out, rows);
}